// round 5
// baseline (speedup 1.0000x reference)
#include <cuda_runtime.h>
#include <math.h>

#define T_LEN    8192
#define NDELAY   360
#define NTHREADS 1024
#define ELEMS    (T_LEN / NTHREADS)      // 8
#define PAD      3392                    // >= 8*L1max = 3352, multiple of 4
#define BUF_LEN  (T_LEN + PAD)
#define SKIP_TH  1e-8f

// ---------------------------------------------------------------------------
// Two-tap IIR (straight-through one-hot is exactly hard in fp32):
//   y = x / (1+s),  s = a1 z^-L1 + a2 z^-L2,  61 <= L1,L2 <= 420
// Squaring:  1/(1+s) = (1-s)(1+s^2).../(1 - s^{2^K})
//   FIR passes (parallel) + chunked serial solve of the remainder.
// Adaptive: remainder differs from identity by ~rho^{2^k}; once below
// 1e-8 the remaining passes / serial phase are skipped (tolerance 1e-3).
// Threads carry their 8 elements in registers across passes (no center LDS).
// Zero-padded buffers -> taps are bare LDS+FFMA, no guards.
// ---------------------------------------------------------------------------

__device__ __forceinline__ float tanh_fast(float x) {
    x = fminf(fmaxf(x, -15.0f), 15.0f);
    float e = __expf(2.0f * x);
    return (e - 1.0f) * __frcp_rn(e + 1.0f);
}

// First pass: reads center from smem, initializes register carry.
template <int NTAPS>
__device__ __forceinline__ void fir_first(float r[ELEMS],
                                          const float* __restrict__ src,
                                          float* __restrict__ dst,
                                          const float* coef, const int* lag,
                                          int tid) {
#pragma unroll
    for (int i = 0; i < ELEMS; i++) {
        const int t = i * NTHREADS + tid;
        float v[NTAPS];
#pragma unroll
        for (int j = 0; j < NTAPS; j++) v[j] = src[t - lag[j]];
        float acc = src[t];
#pragma unroll
        for (int j = 0; j < NTAPS; j++) acc += coef[j] * v[j];
        r[i] = acc;
        dst[t] = acc;
    }
    __syncthreads();
}

// Subsequent passes: center comes from the register carry.
template <int NTAPS>
__device__ __forceinline__ void fir_pass(float r[ELEMS],
                                         const float* __restrict__ src,
                                         float* __restrict__ dst,
                                         const float* coef, const int* lag,
                                         int tid) {
#pragma unroll
    for (int i = 0; i < ELEMS; i++) {
        const int t = i * NTHREADS + tid;
        float v[NTAPS];
#pragma unroll
        for (int j = 0; j < NTAPS; j++) v[j] = src[t - lag[j]];
        float acc = r[i];
#pragma unroll
        for (int j = 0; j < NTAPS; j++) acc += coef[j] * v[j];
        r[i] = acc;
        dst[t] = acc;
    }
    __syncthreads();
}

template <int NTAPS>
__device__ __forceinline__ void iir_chunks(float* __restrict__ buf,
                                           const float* coef, const int* lag,
                                           int W, int tid) {
    for (int s0 = 0; s0 < T_LEN; s0 += W) {
        const int end = (s0 + W < T_LEN) ? (s0 + W) : T_LEN;
        for (int t = s0 + tid; t < end; t += NTHREADS) {
            float v[NTAPS];
#pragma unroll
            for (int j = 0; j < NTAPS; j++) v[j] = buf[t - lag[j]];
            float acc = buf[t];
#pragma unroll
            for (int j = 0; j < NTAPS; j++) acc += coef[j] * v[j];
            buf[t] = acc;
        }
        __syncthreads();
    }
}

__global__ void __launch_bounds__(NTHREADS)
ks_fused_kernel(const float* __restrict__ x,
                const float* __restrict__ gumbel,
                const float* __restrict__ delayp,
                const float* __restrict__ fb,
                const float* __restrict__ rc,
                float* __restrict__ out) {
    extern __shared__ float smem[];
    float* bufA = smem;                 // [BUF_LEN]; data at +PAD
    float* bufB = smem + BUF_LEN;
    float* A = bufA + PAD;
    float* B = bufB + PAD;

    __shared__ float s_rv[32];
    __shared__ int   s_ri[32];
    __shared__ int   s_m;
    __shared__ float s_a1, s_a2;

    const int tid  = threadIdx.x;
    const int row  = blockIdx.x;
    const int lane = tid & 31;
    const int wid  = tid >> 5;

    // --- 1. issue staging loads early (hide DRAM latency under setup) ---
    const float4* x4 = (const float4*)(x + (size_t)row * T_LEN);
    float4 stg[ELEMS / 4];
#pragma unroll
    for (int i = 0; i < ELEMS / 4; i++) stg[i] = x4[tid + i * NTHREADS];

    // --- 2. thread 0: scalar coefficients (fast intrinsics, once) ---
    if (tid == 0) {
        float k1 = tanh_fast(tanh_fast(rc[0]));
        float k2 = tanh_fast(tanh_fast(rc[1]));
        float a1 = k1 * (1.0f - k2);
        float a2 = fminf(fmaxf(k2, -0.999f), 0.999f);
        float bound = 0.999f - fabsf(a2);
        a1 = fminf(fmaxf(a1, -bound), bound);
        float sg = __frcp_rn(1.0f + __expf(-fb[0]));
        float g  = __powf(sg, 0.45f);
        s_a1 = a1 * g;
        s_a2 = a2 * g;
    }

    // --- 3. zero both pads ---
#pragma unroll
    for (int i = 0; i < (PAD + NTHREADS - 1) / NTHREADS; i++) {
        const int p = i * NTHREADS + tid;
        if (p < PAD) { bufA[p] = 0.0f; bufB[p] = 0.0f; }
    }

    // --- 4. argmax over 360 logits (first-index tie-break) ---
    float lv = -INFINITY;
    int   li = tid;
    if (tid < NDELAY) lv = delayp[tid] + gumbel[tid];
#pragma unroll
    for (int off = 16; off > 0; off >>= 1) {
        float ov = __shfl_down_sync(0xffffffffu, lv, off);
        int   oi = __shfl_down_sync(0xffffffffu, li, off);
        if (ov > lv || (ov == lv && oi < li)) { lv = ov; li = oi; }
    }
    if (lane == 0) { s_rv[wid] = lv; s_ri[wid] = li; }
    __syncthreads();
    if (wid == 0) {
        lv = s_rv[lane];
        li = s_ri[lane];
#pragma unroll
        for (int off = 16; off > 0; off >>= 1) {
            float ov = __shfl_down_sync(0xffffffffu, lv, off);
            int   oi = __shfl_down_sync(0xffffffffu, li, off);
            if (ov > lv || (ov == lv && oi < li)) { lv = ov; li = oi; }
        }
        if (lane == 0) s_m = li;
    }

    // --- 5. commit staged x to SMEM ---
    {
        float4* a4 = (float4*)A;
#pragma unroll
        for (int i = 0; i < ELEMS / 4; i++) a4[tid + i * NTHREADS] = stg[i];
    }
    __syncthreads();

    const float a1 = s_a1;
    const float a2 = s_a2;
    const int   m  = s_m;
    const int   L1 = 61 + m;
    const int   L2 = 61 + ((m + 1) % NDELAY);
    const int   C  = (L1 < L2) ? L1 : L2;

    const float rho  = fabsf(a1) + fabsf(a2);
    const float rho2 = rho * rho;
    const float rho4 = rho2 * rho2;
    const float rho8 = rho4 * rho4;

    const float a1_2 = a1 * a1, a2_2 = a2 * a2;
    const float a1_3 = a1_2 * a1, a2_3 = a2_2 * a2;
    const float a1_4 = a1_2 * a1_2, a2_4 = a2_2 * a2_2;

    float r[ELEMS];
    float* res = B;

    // --- pass 1: B = (1 - s) A ---
    {
        const float c[2] = { -a1, -a2 };
        const int   l[2] = { L1, L2 };
        fir_first<2>(r, A, B, c, l, tid);
    }

    if (rho2 >= SKIP_TH) {
        // --- pass 2: A = (1 + s^2) B ---
        {
            const float c[3] = { a1_2, 2.0f * a1 * a2, a2_2 };
            const int   l[3] = { 2 * L1, L1 + L2, 2 * L2 };
            fir_pass<3>(r, B, A, c, l, tid);
        }
        res = A;

        if (rho4 >= SKIP_TH) {
            const float s4c[5] = { a1_4, 4.0f * a1_3 * a2, 6.0f * a1_2 * a2_2,
                                   4.0f * a1 * a2_3, a2_4 };
            const int   s4l[5] = { 4 * L1, 3 * L1 + L2, 2 * L1 + 2 * L2,
                                   L1 + 3 * L2, 4 * L2 };
            if (C <= 150) {
                // --- pass 3: B = (1 + s^4) A; remainder s^8 ---
                fir_pass<5>(r, A, B, s4c, s4l, tid);
                res = B;
                if (rho8 >= SKIP_TH) {
                    const float c[9] = { a1_4 * a1_4, 8.0f * a1_4 * a1_3 * a2,
                                         28.0f * a1_4 * a1_2 * a2_2,
                                         56.0f * a1_4 * a1 * a2_3,
                                         70.0f * a1_4 * a2_4,
                                         56.0f * a1_3 * a2_4 * a2,
                                         28.0f * a1_2 * a2_4 * a2_2,
                                         8.0f * a1 * a2_4 * a2_3,
                                         a2_4 * a2_4 };
                    const int   l[9] = { 8 * L1, 7 * L1 + L2, 6 * L1 + 2 * L2,
                                         5 * L1 + 3 * L2, 4 * L1 + 4 * L2,
                                         3 * L1 + 5 * L2, 2 * L1 + 6 * L2,
                                         L1 + 7 * L2, 8 * L2 };
                    iir_chunks<9>(B, c, l, 8 * C, tid);
                }
            } else {
                // --- remainder s^4 directly (wide C) ---
                iir_chunks<5>(A, s4c, s4l, 4 * C, tid);
                res = A;
            }
        }
    }

    // --- writeback ---
    {
        float4* o4 = (float4*)(out + (size_t)row * T_LEN);
        const float4* r4 = (const float4*)res;
#pragma unroll
        for (int i = 0; i < ELEMS / 4; i++)
            o4[tid + i * NTHREADS] = r4[tid + i * NTHREADS];
    }
}

// ---------------------------------------------------------------------------
// inputs: excitation[128*8192] f32, gumbel[360], delay_param[360],
//         feedback_gain[1], reflection_coeffs[2]; output f32 [128*8192]
// ---------------------------------------------------------------------------
extern "C" void kernel_launch(void* const* d_in, const int* in_sizes, int n_in,
                              void* d_out, int out_size) {
    const float* x      = (const float*)d_in[0];
    const float* gumbel = (const float*)d_in[1];
    const float* delayp = (const float*)d_in[2];
    const float* fb     = (const float*)d_in[3];
    const float* rc     = (const float*)d_in[4];
    float* out = (float*)d_out;

    const int rows = in_sizes[0] / T_LEN;
    const int smem_bytes = 2 * BUF_LEN * sizeof(float);

    cudaFuncSetAttribute(ks_fused_kernel,
                         cudaFuncAttributeMaxDynamicSharedMemorySize, smem_bytes);
    ks_fused_kernel<<<rows, NTHREADS, smem_bytes>>>(x, gumbel, delayp, fb, rc, out);
}